// round 17
// baseline (speedup 1.0000x reference)
#include <cuda_runtime.h>
#include <cstdint>

// out[n,o] = (sum_k xq[n,k]*wq[o,k]) * sx*sw + bias[o]
// xq = round(x * 127/max|x|) clamped [-128,127]; same for w.
// lut[i][j] == (i-128)*(j-128) -> gather is algebraically int8 multiply.
// N = IN = OUT = 512.
// SINGLE kernel, 128 blocks x 256 threads (1 block/SM, co-resident):
//   Phase A: slot-based absmax (blocks 0-63: x, 64-127: w), data in regs
//   hier-barrier 1 -> Phase B: quant from regs -> global fragments (STG.128)
//   hier-barrier 2 -> Phase C: IMMA GEMM (1024 warps, warp tile 16x16)
// Hierarchical barriers: 8 leaves x 16 arrivals -> root x 8; separate
// counter sets per barrier so monotonic round arithmetic stays replay-safe.

#define OO 512

// ---- device scratch (no allocations allowed) ----
__device__ int g_mx8[8 * 64];        // per-slot absmax bits of |x| (256B-strided)
__device__ int g_mw8[8 * 64];        // per-slot absmax bits of |w|
__device__ unsigned g_leaf1[8 * 64]; // barrier 1 leaf counters (monotonic)
__device__ unsigned g_root1;         // barrier 1 root
__device__ unsigned g_leaf2[8 * 64]; // barrier 2 leaf counters (monotonic)
__device__ unsigned g_root2;         // barrier 2 root
__device__ int g_maxx;               // final max bits (same-value race: benign)
__device__ int g_maxw;
__device__ int g_xa[512 * 128];      // A fragments: [rt16][kt32] x 32 lanes x 4 ints
__device__ int g_wb[512 * 128];      // B fragments: [ct8][kt32] x 32 lanes x 2 ints

__device__ __forceinline__ int quant1(float v, float inv) {
    int q = __float2int_rn(v * inv);
    q = max(-128, min(127, q));
    return q & 0xFF;
}
__device__ __forceinline__ int pack4(float4 v, float inv) {
    return quant1(v.x, inv) | (quant1(v.y, inv) << 8) |
           (quant1(v.z, inv) << 16) | (quant1(v.w, inv) << 24);
}

__device__ __forceinline__ void mma_s8(int* c, const int4 a, const int2 b) {
    asm volatile(
        "mma.sync.aligned.m16n8k32.row.col.s32.s8.s8.s32 "
        "{%0,%1,%2,%3}, {%4,%5,%6,%7}, {%8,%9}, {%0,%1,%2,%3};"
        : "+r"(c[0]), "+r"(c[1]), "+r"(c[2]), "+r"(c[3])
        : "r"(a.x), "r"(a.y), "r"(a.z), "r"(a.w), "r"(b.x), "r"(b.y));
}

// Hierarchical grid barrier (thread 0 of each block). Each launch adds
// exactly 16 per leaf and 8 to the root per barrier set -> rounds are
// multiples, monotonic arithmetic is replay-safe with no reset.
__device__ __forceinline__ void hier_barrier(unsigned* leaf, unsigned* root, int bx) {
    const int slot = (bx & 7) * 64;                   // 256B-strided leaves
    unsigned a = atomicAdd(&leaf[slot], 1u) + 1u;     // 16 arrivals/leaf/round
    unsigned n = (a + 15u) >> 4;                      // my round
    if (a == (n << 4)) atomicAdd(root, 1u);           // last of leaf -> root
    while (*(volatile unsigned*)root < (n << 3)) { }  // 8 leaves/round
}

// ------------------------------------------------------------------
__global__ __launch_bounds__(256, 2)
void fused_kernel(const float4* __restrict__ x4, const float4* __restrict__ w4,
                  const float* __restrict__ bias, float* __restrict__ out) {
    __shared__ float sred[8];
    __shared__ float sscale;
    const int tid  = threadIdx.x;
    const int bx   = blockIdx.x;
    const int wid  = tid >> 5;
    const int lane = tid & 31;

    // ---------- Phase A: slot-based loads + absmax ----------
    const bool isA = bx < 64;
    const int g = (bx & 63) * 256 + tid;    // 0..16383 within side

    float4 v0, v1, v2, v3;
    if (isA) {
        int s = g;
        int rt = s >> 9, kt = (s >> 5) & 15, l = s & 31;
        int r  = rt * 16 + (l >> 2);
        int kw = l & 3;
        int off = r * 128 + kt * 8;
        v0 = x4[off + kw];                // (r,   kw)   -> j0
        v1 = x4[off + 1024 + kw];         // (r+8, kw)   -> j1
        v2 = x4[off + kw + 4];            // (r,   kw+4) -> j2
        v3 = x4[off + 1024 + kw + 4];     // (r+8, kw+4) -> j3
    } else {
        int sb = g << 1;                  // even slot
        int ct = sb >> 9, kt = (sb >> 5) & 15, l = sb & 31;
        int c  = ct * 8 + (l >> 2);
        int kw = l & 3;                   // even (0 or 2)
        int off = c * 128 + kt * 8;
        v0 = w4[off + kw];                // slot 2p: (c, kw)
        v1 = w4[off + kw + 4];            // slot 2p: (c, kw+4)
        v2 = w4[off + kw + 1];            // slot 2p+1: (c, kw+1)
        v3 = w4[off + kw + 5];            // slot 2p+1: (c, kw+5)
    }

    float m = fmaxf(fmaxf(fmaxf(fabsf(v0.x), fabsf(v0.y)),
                          fmaxf(fabsf(v0.z), fabsf(v0.w))),
                    fmaxf(fmaxf(fabsf(v1.x), fabsf(v1.y)),
                          fmaxf(fabsf(v1.z), fabsf(v1.w))));
    m = fmaxf(m, fmaxf(fmaxf(fabsf(v2.x), fabsf(v2.y)),
                       fmaxf(fabsf(v2.z), fabsf(v2.w))));
    m = fmaxf(m, fmaxf(fmaxf(fabsf(v3.x), fabsf(v3.y)),
                       fmaxf(fabsf(v3.z), fabsf(v3.w))));
    #pragma unroll
    for (int o = 16; o > 0; o >>= 1)
        m = fmaxf(m, __shfl_xor_sync(0xFFFFFFFFu, m, o));
    if (lane == 0) sred[wid] = m;
    __syncthreads();

    // ---------- barrier 1 (absmax visible) ----------
    if (tid == 0) {
        float bm = sred[0];
        #pragma unroll
        for (int i = 1; i < 8; ++i) bm = fmaxf(bm, sred[i]);
        const int slot = (bx & 7) * 64;
        atomicMax(isA ? &g_mx8[slot] : &g_mw8[slot], __float_as_int(bm));
        __threadfence();
        hier_barrier(g_leaf1, &g_root1, bx);
        __threadfence();
        // fold my tensor's 8 slots; publish final + broadcast scale
        const int* slots = isA ? g_mx8 : g_mw8;
        int fb = slots[0];
        #pragma unroll
        for (int i = 1; i < 8; ++i) fb = max(fb, slots[i * 64]);
        *(isA ? &g_maxx : &g_maxw) = fb;     // same-value race: benign
        sscale = 127.0f / __int_as_float(fb);
    }
    __syncthreads();

    // ---------- Phase B: quantize from registers, one STG.128 ----------
    {
        const float inv = sscale;
        int4 o;
        o.x = pack4(v0, inv);
        o.y = pack4(v1, inv);
        o.z = pack4(v2, inv);
        o.w = pack4(v3, inv);
        ((int4*)(isA ? g_xa : g_wb))[g] = o;
    }

    // ---------- barrier 2 (fragments visible) ----------
    __threadfence();
    __syncthreads();
    if (tid == 0) {
        hier_barrier(g_leaf2, &g_root2, bx);
        __threadfence();
    }
    __syncthreads();

    // ---------- Phase C: IMMA GEMM, warp tile 16(M) x 16(N) ----------
    const int wt  = bx * 8 + wid;          // 0..1023
    const int rt  = wt >> 5;               // 0..31
    const int ct0 = (wt & 31) << 1;        // 0..62

    const int4* __restrict__ XA = (const int4*)g_xa;
    const int2* __restrict__ WB = (const int2*)g_wb;

    int acc[2][4];
    #pragma unroll
    for (int n = 0; n < 2; ++n)
        #pragma unroll
        for (int j = 0; j < 4; ++j) acc[n][j] = 0;

    #pragma unroll
    for (int kt = 0; kt < 16; ++kt) {
        int4 a  = XA[(rt * 16 + kt) * 32 + lane];
        int2 b0 = WB[((ct0 + 0) * 16 + kt) * 32 + lane];
        int2 b1 = WB[((ct0 + 1) * 16 + kt) * 32 + lane];
        mma_s8(acc[0], a, b0);
        mma_s8(acc[1], a, b1);
    }

    // ---------- epilogue ----------
    const float fmx = __int_as_float(*(volatile int*)&g_maxx);
    const float fmw = __int_as_float(*(volatile int*)&g_maxw);
    const float sc  = (fmx / 127.0f) * (fmw / 127.0f);
    const int gr  = lane >> 2;
    const int tig = lane & 3;
    #pragma unroll
    for (int n = 0; n < 2; ++n) {
        int col = (ct0 + n) * 8 + tig * 2;
        float2 bb = *(const float2*)&bias[col];
        int row = rt * 16 + gr;
        float2 u0 = { (float)acc[n][0] * sc + bb.x, (float)acc[n][1] * sc + bb.y };
        float2 u1 = { (float)acc[n][2] * sc + bb.x, (float)acc[n][3] * sc + bb.y };
        *(float2*)&out[row * OO + col]       = u0;
        *(float2*)&out[(row + 8) * OO + col] = u1;
    }
}

// ------------------------------------------------------------------
extern "C" void kernel_launch(void* const* d_in, const int* in_sizes, int n_in,
                              void* d_out, int out_size) {
    const float* x    = (const float*)d_in[0];   // [512,512]
    const float* w    = (const float*)d_in[1];   // [512,512]
    const float* bias = (const float*)d_in[2];   // [512]
    float* out = (float*)d_out;

    fused_kernel<<<128, 256>>>((const float4*)x, (const float4*)w, bias, out);
}